// round 16
// baseline (speedup 1.0000x reference)
#include <cuda_runtime.h>
#include <cuda_bf16.h>
#include <mma.h>
#include <cstdint>
#include <cstddef>

using namespace nvcuda;

// Problem constants
#define B_   4
#define L_   1024
#define D_   512
#define H_   8
#define EK_  64
#define PADF 32
#define M_   (B_ * L_)    // 4096
#define KSTORE 1024       // stored K: [hi | lo]; 3 compensated products via offsets

// ---------------------------------------------------------------------------
// Scratch (device globals -- no runtime allocation allowed)
// g_q / g_k double as out-proj split-K partial buffers after attention.
// ---------------------------------------------------------------------------
__device__ float g_q[M_ * D_];
__device__ float g_k[M_ * D_];
__device__ float g_v[M_ * D_];
__device__ __align__(256) __nv_bfloat16 g_in2[3ull * M_ * KSTORE];
__device__ __align__(256) __nv_bfloat16 g_attn2[(size_t)M_ * KSTORE];
__device__ __align__(256) __nv_bfloat16 g_w2[4ull * D_ * KSTORE];

// ---------------------------------------------------------------------------
// 2-way split helpers
// ---------------------------------------------------------------------------
__device__ __forceinline__ void split2(float x, __nv_bfloat16& hi,
                                       __nv_bfloat16& lo)
{
    hi = __float2bfloat16(x);
    lo = __float2bfloat16(x - __bfloat162float(hi));
}

__device__ __forceinline__ uint32_t pack2(__nv_bfloat16 a, __nv_bfloat16 b)
{
    __nv_bfloat162 t(a, b);
    return *reinterpret_cast<uint32_t*>(&t);
}

__device__ __forceinline__ void split4(float4 x, uint2& hi2, uint2& lo2)
{
    __nv_bfloat16 h0, h1, h2, h3, l0, l1, l2, l3;
    split2(x.x, h0, l0); split2(x.y, h1, l1);
    split2(x.z, h2, l2); split2(x.w, h3, l3);
    hi2 = make_uint2(pack2(h0, h1), pack2(h2, h3));
    lo2 = make_uint2(pack2(l0, l1), pack2(l2, l3));
}

__global__ __launch_bounds__(256) void split_in_kernel(
    const float* __restrict__ q, const float* __restrict__ k,
    const float* __restrict__ v)
{
    int i = blockIdx.x * 256 + threadIdx.x;           // over M_*D_/4
    int s = blockIdx.y;
    const float* S = (s == 0) ? q : (s == 1) ? k : v;
    int e = i * 4;
    float4 x = *(const float4*)(S + e);
    uint2 hi2, lo2;
    split4(x, hi2, lo2);
    int r = e >> 9, c = e & 511;
    __nv_bfloat16* dst = g_in2 + (size_t)s * M_ * KSTORE
                               + (size_t)r * KSTORE + c;
    *(uint2*)(dst)       = hi2;
    *(uint2*)(dst + 512) = lo2;
}

// Weights: W[K=512][N=512] row-major -> Wt[n][j]=hi, Wt[n][512+j]=lo
__global__ __launch_bounds__(256) void split_w_kernel(
    const float* __restrict__ Wq, const float* __restrict__ Wk,
    const float* __restrict__ Wv, const float* __restrict__ Wo)
{
    __shared__ float tile[64][65];
    int z = blockIdx.z;
    const float* W = (z == 0) ? Wq : (z == 1) ? Wk : (z == 2) ? Wv : Wo;
    int j0 = blockIdx.x * 64, n0 = blockIdx.y * 64;
    for (int i = threadIdx.x; i < 4096; i += 256) {
        int r = i >> 6, c = i & 63;
        tile[r][c] = W[(size_t)(j0 + r) * D_ + n0 + c];
    }
    __syncthreads();
    __nv_bfloat16* dst = g_w2 + (size_t)z * D_ * KSTORE;
    for (int i = threadIdx.x; i < 1024; i += 256) {
        int r = i >> 4, c4 = (i & 15) * 4;
        float4 x = make_float4(tile[c4][r], tile[c4 + 1][r],
                               tile[c4 + 2][r], tile[c4 + 3][r]);
        uint2 hi2, lo2;
        split4(x, hi2, lo2);
        __nv_bfloat16* row = dst + (size_t)(n0 + r) * KSTORE;
        *(uint2*)(row + j0 + c4)       = hi2;
        *(uint2*)(row + 512 + j0 + c4) = lo2;
    }
}

// ---------------------------------------------------------------------------
// wmma bf16 GEMM core (round-14: A-reuse schedule, 128x128 tile, 8 warps,
// NST=3, 2 CTAs/SM). Shared by the full-K qkv kernel and the split-K
// out-proj kernel (kt range [KT0, KT0+KTN)).
// ---------------------------------------------------------------------------
#define BK 64
#define STR 72                       // smem row stride (bf16), 144B
#define NKT 24
#define A_ELEMS (128 * STR)          // 9216
#define B_ELEMS (128 * STR)          // 9216
#define NSTAGE 3
#define GEMM_SMEM (NSTAGE * (A_ELEMS + B_ELEMS) * 2)   // 110592 B

__device__ __forceinline__ void cp16(uint32_t dst, const void* src) {
    asm volatile("cp.async.cg.shared.global [%0], [%1], 16;"
                 :: "r"(dst), "l"(src));
}

__device__ __forceinline__ uint32_t smem_u32(const void* p) {
    uint32_t a;
    asm("{ .reg .u64 t; cvta.to.shared.u64 t, %1; cvt.u32.u64 %0, t; }"
        : "=r"(a) : "l"(p));
    return a;
}

// A-reuse schedule helpers (absolute kt)
__device__ __forceinline__ bool kt_aload(int kt) {
    return (kt >= 16) || ((kt & 1) == 0);
}
__device__ __forceinline__ int kt_aidx(int kt) {
    return (kt < 16) ? (kt >> 1) : (8 + (kt - 16));
}
__device__ __forceinline__ int kt_aoff(int kt) {
    return (kt < 16) ? ((kt >> 1) * 64) : (512 + (kt - 16) * 64);
}
__device__ __forceinline__ int kt_boff(int kt) {
    return (kt < 16) ? (((kt & 1) ? 512 : 0) + (kt >> 1) * 64)
                     : ((kt - 16) * 64);
}

__device__ __forceinline__ void tile_loads(const __nv_bfloat16* __restrict__ G,
                                           uint32_t sbase, int t)
{
    #pragma unroll
    for (int i = 0; i < 4; i++) {
        int idx = t + i * 256;
        int row = idx >> 3, c = idx & 7;
        cp16(sbase + (uint32_t)(row * (STR * 2) + c * 16),
             G + (size_t)row * KSTORE + c * 8);
    }
}

// Core mainloop over kt in [kt0, kt0+ktn). Accumulators in cf.
__device__ __forceinline__ void gemm_core(
    const __nv_bfloat16* __restrict__ Abase,
    const __nv_bfloat16* __restrict__ Bbase,
    uint32_t sAb, uint32_t sBb,
    __nv_bfloat16* sA, __nv_bfloat16* sB,
    wmma::fragment<wmma::accumulator, 16, 16, 16, float> (&cf)[4][2],
    int t, int wm, int wn, int kt0, int ktn)
{
    const int ktend = kt0 + ktn;

    // prologue: stages kt0, kt0+1
    tile_loads(Abase + kt_aoff(kt0), sAb + (kt_aidx(kt0) % 3) * (A_ELEMS * 2), t);
    tile_loads(Bbase + kt_boff(kt0), sBb + (kt0 % 3) * (B_ELEMS * 2), t);
    asm volatile("cp.async.commit_group;");
    if (kt_aload(kt0 + 1))
        tile_loads(Abase + kt_aoff(kt0 + 1),
                   sAb + (kt_aidx(kt0 + 1) % 3) * (A_ELEMS * 2), t);
    tile_loads(Bbase + kt_boff(kt0 + 1),
               sBb + ((kt0 + 1) % 3) * (B_ELEMS * 2), t);
    asm volatile("cp.async.commit_group;");

    #pragma unroll 1
    for (int kt = kt0; kt < ktend; kt++) {
        asm volatile("cp.async.wait_group 1;");
        __syncthreads();
        if (kt + 2 < ktend) {
            if (kt_aload(kt + 2))
                tile_loads(Abase + kt_aoff(kt + 2),
                           sAb + (kt_aidx(kt + 2) % 3) * (A_ELEMS * 2), t);
            tile_loads(Bbase + kt_boff(kt + 2),
                       sBb + ((kt + 2) % 3) * (B_ELEMS * 2), t);
        }
        asm volatile("cp.async.commit_group;");

        const __nv_bfloat16* sa = sA + (kt_aidx(kt) % 3) * A_ELEMS;
        const __nv_bfloat16* sb = sB + (kt % 3) * B_ELEMS;
        #pragma unroll
        for (int kk = 0; kk < BK; kk += 16) {
            wmma::fragment<wmma::matrix_a, 16, 16, 16, __nv_bfloat16,
                           wmma::row_major> af[4];
            wmma::fragment<wmma::matrix_b, 16, 16, 16, __nv_bfloat16,
                           wmma::col_major> bf[2];
            #pragma unroll
            for (int i = 0; i < 4; i++)
                wmma::load_matrix_sync(af[i],
                    sa + (wm * 64 + i * 16) * STR + kk, STR);
            #pragma unroll
            for (int j = 0; j < 2; j++)
                wmma::load_matrix_sync(bf[j],
                    sb + (wn * 32 + j * 16) * STR + kk, STR);
            #pragma unroll
            for (int i = 0; i < 4; i++)
                #pragma unroll
                for (int j = 0; j < 2; j++)
                    wmma::mma_sync(cf[i][j], af[i], bf[j], cf[i][j]);
        }
    }
}

__global__ __launch_bounds__(256, 2) void gemm3_kernel(
    const __nv_bfloat16* __restrict__ A0, const __nv_bfloat16* __restrict__ A1,
    const __nv_bfloat16* __restrict__ A2,
    const __nv_bfloat16* __restrict__ Bw0, const __nv_bfloat16* __restrict__ Bw1,
    const __nv_bfloat16* __restrict__ Bw2,
    float* __restrict__ C0, float* __restrict__ C1, float* __restrict__ C2)
{
    extern __shared__ __align__(256) __nv_bfloat16 gsm[];
    __nv_bfloat16* sA = gsm;
    __nv_bfloat16* sB = gsm + NSTAGE * A_ELEMS;

    const int z = blockIdx.z;
    const __nv_bfloat16* A  = (z == 0) ? A0  : (z == 1) ? A1  : A2;
    const __nv_bfloat16* Bw = (z == 0) ? Bw0 : (z == 1) ? Bw1 : Bw2;
    float* C                = (z == 0) ? C0  : (z == 1) ? C1  : C2;

    const int t   = threadIdx.x;
    const int wid = t >> 5;
    const int wm  = wid & 1;
    const int wn  = wid >> 1;
    const int m0  = blockIdx.y * 128, n0 = blockIdx.x * 128;

    wmma::fragment<wmma::accumulator, 16, 16, 16, float> cf[4][2];
    #pragma unroll
    for (int i = 0; i < 4; i++)
        #pragma unroll
        for (int j = 0; j < 2; j++) wmma::fill_fragment(cf[i][j], 0.f);

    gemm_core(A + (size_t)m0 * KSTORE, Bw + (size_t)n0 * KSTORE,
              smem_u32(sA), smem_u32(sB), sA, sB, cf, t, wm, wn, 0, NKT);

    #pragma unroll
    for (int i = 0; i < 4; i++)
        #pragma unroll
        for (int j = 0; j < 2; j++)
            wmma::store_matrix_sync(
                C + (size_t)(m0 + wm * 64 + i * 16) * D_ + n0 + wn * 32 + j * 16,
                cf[i][j], D_, wmma::mem_row_major);
}

// Split-K out-proj: blockIdx.z = k-half (kt 0..11 -> P0, kt 12..23 -> P1)
__global__ __launch_bounds__(256, 2) void gemm_splitk_kernel(
    const __nv_bfloat16* __restrict__ A, const __nv_bfloat16* __restrict__ Bw,
    float* __restrict__ P0, float* __restrict__ P1)
{
    extern __shared__ __align__(256) __nv_bfloat16 gsm[];
    __nv_bfloat16* sA = gsm;
    __nv_bfloat16* sB = gsm + NSTAGE * A_ELEMS;

    const int z  = blockIdx.z;
    float* P     = z ? P1 : P0;
    const int t   = threadIdx.x;
    const int wid = t >> 5;
    const int wm  = wid & 1;
    const int wn  = wid >> 1;
    const int m0  = blockIdx.y * 128, n0 = blockIdx.x * 128;

    wmma::fragment<wmma::accumulator, 16, 16, 16, float> cf[4][2];
    #pragma unroll
    for (int i = 0; i < 4; i++)
        #pragma unroll
        for (int j = 0; j < 2; j++) wmma::fill_fragment(cf[i][j], 0.f);

    gemm_core(A + (size_t)m0 * KSTORE, Bw + (size_t)n0 * KSTORE,
              smem_u32(sA), smem_u32(sB), sA, sB, cf, t, wm, wn,
              z * 12, 12);

    #pragma unroll
    for (int i = 0; i < 4; i++)
        #pragma unroll
        for (int j = 0; j < 2; j++)
            wmma::store_matrix_sync(
                P + (size_t)(m0 + wm * 64 + i * 16) * D_ + n0 + wn * 32 + j * 16,
                cf[i][j], D_, wmma::mem_row_major);
}

__global__ __launch_bounds__(256) void reduce_kernel(
    const float* __restrict__ p0, const float* __restrict__ p1,
    float* __restrict__ out)
{
    int i = (blockIdx.x * 256 + threadIdx.x) * 4;
    float4 a = *(const float4*)(p0 + i);
    float4 b = *(const float4*)(p1 + i);
    *(float4*)(out + i) = make_float4(a.x + b.x, a.y + b.y,
                                      a.z + b.z, a.w + b.w);
}

// ---------------------------------------------------------------------------
// wmma banded local attention (unchanged from rounds 9-14).
// ---------------------------------------------------------------------------
#define AQLD 72
#define ASLD 84
#define APLD 88
#define AOLD 68

#define AOFF_Q 0
#define AOFF_K (AOFF_Q + 2 * 64 * AQLD * 2)
#define AOFF_V (AOFF_K + 2 * 128 * AQLD * 2)
#define AOFF_S (AOFF_V + 2 * 128 * AQLD * 2)
#define SMEM_ATTN (AOFF_S + 64 * ASLD * 4)         // 113664

__global__ __launch_bounds__(256, 2) void attn_wmma_kernel(
    const float* __restrict__ Q, const float* __restrict__ Kp,
    const float* __restrict__ Vp, const unsigned char* __restrict__ mask,
    __nv_bfloat16* __restrict__ Out2)
{
    extern __shared__ __align__(256) char sm[];
    __nv_bfloat16* sQhi = (__nv_bfloat16*)(sm + AOFF_Q);
    __nv_bfloat16* sQlo = sQhi + 64 * AQLD;
    __nv_bfloat16* sKhi = (__nv_bfloat16*)(sm + AOFF_K);
    __nv_bfloat16* sKlo = sKhi + 128 * AQLD;
    __nv_bfloat16* sVhi = (__nv_bfloat16*)(sm + AOFF_V);
    __nv_bfloat16* sVlo = sVhi + 128 * AQLD;
    float*         sS   = (float*)(sm + AOFF_S);
    __nv_bfloat16* sPhi = (__nv_bfloat16*)(sm + AOFF_Q);
    __nv_bfloat16* sPlo = sPhi + 64 * APLD;
    float*         sO   = sS;

    const int l0 = blockIdx.x * 64;
    const int h  = blockIdx.y;
    const int b  = blockIdx.z;
    const int t  = threadIdx.x;
    const int w  = t >> 5;

    const size_t headoff = (size_t)h * EK_;
    const float* Qbase = Q  + (size_t)b * L_ * D_ + headoff;
    const float* Kbase = Kp + (size_t)b * L_ * D_ + headoff;
    const float* Vbase = Vp + (size_t)b * L_ * D_ + headoff;

    for (int i = t; i < 64 * 16; i += 256) {
        int row = i >> 4, c = (i & 15) << 2;
        float4 x = *(const float4*)(Qbase + (size_t)(l0 + row) * D_ + c);
        uint2 hi2, lo2;
        split4(x, hi2, lo2);
        *(uint2*)(sQhi + row * AQLD + c) = hi2;
        *(uint2*)(sQlo + row * AQLD + c) = lo2;
    }
    for (int i = t; i < 128 * 16; i += 256) {
        int row = i >> 4, c = (i & 15) << 2;
        int gl = l0 - PADF + row;
        bool in = (gl >= 0) && (gl < L_);
        float4 xk = in ? *(const float4*)(Kbase + (size_t)gl * D_ + c)
                       : make_float4(0.f, 0.f, 0.f, 0.f);
        float4 xv = in ? *(const float4*)(Vbase + (size_t)gl * D_ + c)
                       : make_float4(0.f, 0.f, 0.f, 0.f);
        uint2 khi, klo, vhi, vlo;
        split4(xk, khi, klo);
        split4(xv, vhi, vlo);
        *(uint2*)(sKhi + row * AQLD + c) = khi;
        *(uint2*)(sKlo + row * AQLD + c) = klo;
        *(uint2*)(sVhi + row * AQLD + c) = vhi;
        *(uint2*)(sVlo + row * AQLD + c) = vlo;
    }
    __syncthreads();

    {
        const int rg   = w >> 1;
        const int half = w & 1;
        const int j0   = half ? 3 : 0;
        const int nj   = half ? 2 : 3;

        wmma::fragment<wmma::accumulator, 16, 16, 16, float> sf[3];
        #pragma unroll
        for (int j = 0; j < 3; j++) wmma::fill_fragment(sf[j], 0.f);

        #pragma unroll
        for (int tm = 0; tm < 3; tm++) {
            const __nv_bfloat16* Qsrc = (tm == 2) ? sQlo : sQhi;
            const __nv_bfloat16* Ksrc = (tm == 1) ? sKlo : sKhi;
            #pragma unroll
            for (int kk = 0; kk < 64; kk += 16) {
                wmma::fragment<wmma::matrix_a, 16, 16, 16, __nv_bfloat16,
                               wmma::row_major> qa;
                wmma::load_matrix_sync(qa, Qsrc + rg * 16 * AQLD + kk, AQLD);
                #pragma unroll
                for (int j = 0; j < 3; j++) {
                    if (j < nj) {
                        wmma::fragment<wmma::matrix_b, 16, 16, 16, __nv_bfloat16,
                                       wmma::col_major> kb;
                        wmma::load_matrix_sync(kb,
                            Ksrc + (rg * 16 + (j0 + j) * 16) * AQLD + kk, AQLD);
                        wmma::mma_sync(sf[j], qa, kb, sf[j]);
                    }
                }
            }
        }
        #pragma unroll
        for (int j = 0; j < 3; j++)
            if (j < nj)
                wmma::store_matrix_sync(sS + rg * 16 * ASLD + (j0 + j) * 16,
                                        sf[j], ASLD, wmma::mem_row_major);
    }
    __syncthreads();

    {
        const int g     = t >> 2;
        const int lane4 = t & 3;
        const int G     = g >> 4;
        const int off   = g & 15;
        const int gl0   = l0 - PADF + 16 * G;
        const unsigned char* mrow = mask + (size_t)b * L_;

        float sv[16];
        #pragma unroll
        for (int i = 0; i < 16; i++) {
            int r  = off + lane4 * 16 + i;
            int gl = gl0 + r;
            bool valid = (gl >= 0) && (gl < L_) && (mrow[gl] == 0);
            sv[i] = valid ? sS[g * ASLD + r] : -1e30f;
        }
        float m = sv[0];
        #pragma unroll
        for (int i = 1; i < 16; i++) m = fmaxf(m, sv[i]);
        m = fmaxf(m, __shfl_xor_sync(0xffffffffu, m, 1));
        m = fmaxf(m, __shfl_xor_sync(0xffffffffu, m, 2));
        float sum = 0.f;
        #pragma unroll
        for (int i = 0; i < 16; i++) { sv[i] = __expf(sv[i] - m); sum += sv[i]; }
        sum += __shfl_xor_sync(0xffffffffu, sum, 1);
        sum += __shfl_xor_sync(0xffffffffu, sum, 2);
        float inv = 1.f / sum;

        __nv_bfloat16 z0 = __float2bfloat16(0.f);
        #pragma unroll
        for (int i = 0; i < 20; i++) {
            int r = lane4 * 20 + i;
            sPhi[g * APLD + r] = z0;
            sPlo[g * APLD + r] = z0;
        }
        #pragma unroll
        for (int i = 0; i < 16; i++) {
            int r = off + lane4 * 16 + i;
            __nv_bfloat16 hi, lo;
            split2(sv[i] * inv, hi, lo);
            sPhi[g * APLD + r] = hi;
            sPlo[g * APLD + r] = lo;
        }
    }
    __syncthreads();

    {
        const int rg   = w >> 1;
        const int half = w & 1;

        wmma::fragment<wmma::accumulator, 16, 16, 16, float> of[2];
        #pragma unroll
        for (int j = 0; j < 2; j++) wmma::fill_fragment(of[j], 0.f);

        #pragma unroll
        for (int tm = 0; tm < 3; tm++) {
            const __nv_bfloat16* Psrc = (tm == 2) ? sPlo : sPhi;
            const __nv_bfloat16* Vsrc = (tm == 1) ? sVlo : sVhi;
            #pragma unroll
            for (int kk = 0; kk < 80; kk += 16) {
                wmma::fragment<wmma::matrix_a, 16, 16, 16, __nv_bfloat16,
                               wmma::row_major> pa;
                wmma::load_matrix_sync(pa, Psrc + rg * 16 * APLD + kk, APLD);
                #pragma unroll
                for (int j = 0; j < 2; j++) {
                    wmma::fragment<wmma::matrix_b, 16, 16, 16, __nv_bfloat16,
                                   wmma::row_major> vb;
                    wmma::load_matrix_sync(vb,
                        Vsrc + (rg * 16 + kk) * AQLD + (half * 2 + j) * 16, AQLD);
                    wmma::mma_sync(of[j], pa, vb, of[j]);
                }
            }
        }
        #pragma unroll
        for (int j = 0; j < 2; j++)
            wmma::store_matrix_sync(sO + rg * 16 * AOLD + (half * 2 + j) * 16,
                                    of[j], AOLD, wmma::mem_row_major);
    }
    __syncthreads();

    for (int i = t; i < 64 * 16; i += 256) {
        int row = i >> 4, c = (i & 15) << 2;
        float4 x = *(const float4*)(sO + row * AOLD + c);
        uint2 hi2, lo2;
        split4(x, hi2, lo2);
        __nv_bfloat16* dst = Out2 + (size_t)(b * L_ + l0 + row) * KSTORE
                                  + headoff + c;
        *(uint2*)(dst)       = hi2;
        *(uint2*)(dst + 512) = lo2;
    }
}

// ---------------------------------------------------------------------------
// Launch
// ---------------------------------------------------------------------------
extern "C" void kernel_launch(void* const* d_in, const int* in_sizes, int n_in,
                              void* d_out, int out_size)
{
    const float* query = (const float*)d_in[0];
    const float* key   = (const float*)d_in[1];
    const float* value = (const float*)d_in[2];
    const unsigned char* mask = (const unsigned char*)d_in[3];
    const float* Wq = (const float*)d_in[5];
    const float* Wk = (const float*)d_in[6];
    const float* Wv = (const float*)d_in[7];
    const float* Wo = (const float*)d_in[8];
    float* out = (float*)d_out;

    float *dq, *dk, *dv;
    __nv_bfloat16 *din2, *dat2, *dw2;
    cudaGetSymbolAddress((void**)&dq, g_q);
    cudaGetSymbolAddress((void**)&dk, g_k);
    cudaGetSymbolAddress((void**)&dv, g_v);
    cudaGetSymbolAddress((void**)&din2, g_in2);
    cudaGetSymbolAddress((void**)&dat2, g_attn2);
    cudaGetSymbolAddress((void**)&dw2, g_w2);

    cudaFuncSetAttribute(attn_wmma_kernel,
                         cudaFuncAttributeMaxDynamicSharedMemorySize, SMEM_ATTN);
    cudaFuncSetAttribute(gemm3_kernel,
                         cudaFuncAttributeMaxDynamicSharedMemorySize, GEMM_SMEM);
    cudaFuncSetAttribute(gemm_splitk_kernel,
                         cudaFuncAttributeMaxDynamicSharedMemorySize, GEMM_SMEM);

    // 1) split inputs + weights into [hi|lo] bf16
    split_in_kernel<<<dim3(M_ * D_ / 1024, 3), 256>>>(query, key, value);
    split_w_kernel<<<dim3(8, 8, 4), 256>>>(Wq, Wk, Wv, Wo);

    // 2) QKV projections: 3 GEMMs in one tensor-core launch
    const __nv_bfloat16* Aq = din2;
    const __nv_bfloat16* Ak = din2 + (size_t)1 * M_ * KSTORE;
    const __nv_bfloat16* Av = din2 + (size_t)2 * M_ * KSTORE;
    const __nv_bfloat16* Bq = dw2;
    const __nv_bfloat16* Bk = dw2 + (size_t)1 * D_ * KSTORE;
    const __nv_bfloat16* Bv = dw2 + (size_t)2 * D_ * KSTORE;
    const __nv_bfloat16* Bo = dw2 + (size_t)3 * D_ * KSTORE;
    gemm3_kernel<<<dim3(D_ / 128, M_ / 128, 3), 256, GEMM_SMEM>>>(
        Aq, Ak, Av, Bq, Bk, Bv, dq, dk, dv);

    // 3) banded local attention (wmma); writes split O directly
    attn_wmma_kernel<<<dim3(16, 8, 4), 256, SMEM_ATTN>>>(dq, dk, dv, mask, dat2);

    // 4) output projection, split-K=2 (partials into dq/dk, now dead) + reduce
    gemm_splitk_kernel<<<dim3(D_ / 128, M_ / 128, 2), 256, GEMM_SMEM>>>(
        dat2, Bo, dq, dk);
    reduce_kernel<<<M_ * D_ / 1024, 256>>>(dq, dk, out);
}

// round 17
// speedup vs baseline: 1.0421x; 1.0421x over previous
#include <cuda_runtime.h>
#include <cuda_bf16.h>
#include <mma.h>
#include <cstdint>
#include <cstddef>

using namespace nvcuda;

// Problem constants
#define B_   4
#define L_   1024
#define D_   512
#define H_   8
#define EK_  64
#define PADF 32
#define M_   (B_ * L_)    // 4096
#define KSTORE 1024       // stored K: [hi | lo]; 3 compensated products via offsets
#define QROW 1024         // g_qkv2 row stride: H_ heads x [hi64|lo64] bf16

// ---------------------------------------------------------------------------
// Scratch (device globals -- no runtime allocation allowed)
// ---------------------------------------------------------------------------
__device__ __align__(256) __nv_bfloat16 g_qkv2[3ull * M_ * QROW]; // split q,k,v (per head)
__device__ __align__(256) __nv_bfloat16 g_in2[3ull * M_ * KSTORE];
__device__ __align__(256) __nv_bfloat16 g_attn2[(size_t)M_ * KSTORE];
__device__ __align__(256) __nv_bfloat16 g_w2[4ull * D_ * KSTORE];

// ---------------------------------------------------------------------------
// 2-way split helpers
// ---------------------------------------------------------------------------
__device__ __forceinline__ void split2(float x, __nv_bfloat16& hi,
                                       __nv_bfloat16& lo)
{
    hi = __float2bfloat16(x);
    lo = __float2bfloat16(x - __bfloat162float(hi));
}

__device__ __forceinline__ uint32_t pack2(__nv_bfloat16 a, __nv_bfloat16 b)
{
    __nv_bfloat162 t(a, b);
    return *reinterpret_cast<uint32_t*>(&t);
}

__device__ __forceinline__ void split4(float4 x, uint2& hi2, uint2& lo2)
{
    __nv_bfloat16 h0, h1, h2, h3, l0, l1, l2, l3;
    split2(x.x, h0, l0); split2(x.y, h1, l1);
    split2(x.z, h2, l2); split2(x.w, h3, l3);
    hi2 = make_uint2(pack2(h0, h1), pack2(h2, h3));
    lo2 = make_uint2(pack2(l0, l1), pack2(l2, l3));
}

__global__ __launch_bounds__(256) void split_in_kernel(
    const float* __restrict__ q, const float* __restrict__ k,
    const float* __restrict__ v)
{
    int i = blockIdx.x * 256 + threadIdx.x;           // over M_*D_/4
    int s = blockIdx.y;
    const float* S = (s == 0) ? q : (s == 1) ? k : v;
    int e = i * 4;
    float4 x = *(const float4*)(S + e);
    uint2 hi2, lo2;
    split4(x, hi2, lo2);
    int r = e >> 9, c = e & 511;
    __nv_bfloat16* dst = g_in2 + (size_t)s * M_ * KSTORE
                               + (size_t)r * KSTORE + c;
    *(uint2*)(dst)       = hi2;
    *(uint2*)(dst + 512) = lo2;
}

// Weights: W[K=512][N=512] row-major -> Wt[n][j]=hi, Wt[n][512+j]=lo
__global__ __launch_bounds__(256) void split_w_kernel(
    const float* __restrict__ Wq, const float* __restrict__ Wk,
    const float* __restrict__ Wv, const float* __restrict__ Wo)
{
    __shared__ float tile[64][65];
    int z = blockIdx.z;
    const float* W = (z == 0) ? Wq : (z == 1) ? Wk : (z == 2) ? Wv : Wo;
    int j0 = blockIdx.x * 64, n0 = blockIdx.y * 64;
    for (int i = threadIdx.x; i < 4096; i += 256) {
        int r = i >> 6, c = i & 63;
        tile[r][c] = W[(size_t)(j0 + r) * D_ + n0 + c];
    }
    __syncthreads();
    __nv_bfloat16* dst = g_w2 + (size_t)z * D_ * KSTORE;
    for (int i = threadIdx.x; i < 1024; i += 256) {
        int r = i >> 4, c4 = (i & 15) * 4;
        float4 x = make_float4(tile[c4][r], tile[c4 + 1][r],
                               tile[c4 + 2][r], tile[c4 + 3][r]);
        uint2 hi2, lo2;
        split4(x, hi2, lo2);
        __nv_bfloat16* row = dst + (size_t)(n0 + r) * KSTORE;
        *(uint2*)(row + j0 + c4)       = hi2;
        *(uint2*)(row + 512 + j0 + c4) = lo2;
    }
}

// ---------------------------------------------------------------------------
// wmma bf16 GEMM (round-14: A-reuse schedule, 128x128 tile, 8 warps,
// NST=3, 2 CTAs/SM). SPLITOUT=true: epilogue split-writes bf16 [hi|lo] per
// head into g_qkv2 layout; SPLITOUT=false: plain fp32 store (out-proj).
// ---------------------------------------------------------------------------
#define BK 64
#define STR 72
#define NKT 24
#define A_ELEMS (128 * STR)          // 9216
#define B_ELEMS (128 * STR)          // 9216
#define NSTAGE 3
#define GEMM_SMEM (NSTAGE * (A_ELEMS + B_ELEMS) * 2)   // 110592 B

__device__ __forceinline__ void cp16(uint32_t dst, const void* src) {
    asm volatile("cp.async.cg.shared.global [%0], [%1], 16;"
                 :: "r"(dst), "l"(src));
}

// cp.async with runtime src-size (0 => zero-fill)
__device__ __forceinline__ void cp16z(uint32_t dst, const void* src,
                                      uint32_t srcsize) {
    asm volatile("cp.async.cg.shared.global [%0], [%1], 16, %2;"
                 :: "r"(dst), "l"(src), "r"(srcsize));
}

__device__ __forceinline__ uint32_t smem_u32(const void* p) {
    uint32_t a;
    asm("{ .reg .u64 t; cvta.to.shared.u64 t, %1; cvt.u32.u64 %0, t; }"
        : "=r"(a) : "l"(p));
    return a;
}

// A-reuse schedule helpers (absolute kt)
__device__ __forceinline__ bool kt_aload(int kt) {
    return (kt >= 16) || ((kt & 1) == 0);
}
__device__ __forceinline__ int kt_aidx(int kt) {
    return (kt < 16) ? (kt >> 1) : (8 + (kt - 16));
}
__device__ __forceinline__ int kt_aoff(int kt) {
    return (kt < 16) ? ((kt >> 1) * 64) : (512 + (kt - 16) * 64);
}
__device__ __forceinline__ int kt_boff(int kt) {
    return (kt < 16) ? (((kt & 1) ? 512 : 0) + (kt >> 1) * 64)
                     : ((kt - 16) * 64);
}

__device__ __forceinline__ void tile_loads(const __nv_bfloat16* __restrict__ G,
                                           uint32_t sbase, int t)
{
    #pragma unroll
    for (int i = 0; i < 4; i++) {
        int idx = t + i * 256;
        int row = idx >> 3, c = idx & 7;
        cp16(sbase + (uint32_t)(row * (STR * 2) + c * 16),
             G + (size_t)row * KSTORE + c * 8);
    }
}

template <bool SPLITOUT>
__global__ __launch_bounds__(256, 2) void gemm3_kernel(
    const __nv_bfloat16* __restrict__ A0, const __nv_bfloat16* __restrict__ A1,
    const __nv_bfloat16* __restrict__ A2,
    const __nv_bfloat16* __restrict__ Bw0, const __nv_bfloat16* __restrict__ Bw1,
    const __nv_bfloat16* __restrict__ Bw2,
    void* __restrict__ C0v, void* __restrict__ C1v, void* __restrict__ C2v)
{
    extern __shared__ __align__(256) __nv_bfloat16 gsm[];
    __nv_bfloat16* sA = gsm;                          // [NSTAGE][A_ELEMS]
    __nv_bfloat16* sB = gsm + NSTAGE * A_ELEMS;       // [NSTAGE][B_ELEMS]

    const int z = blockIdx.z;
    const __nv_bfloat16* A  = (z == 0) ? A0  : (z == 1) ? A1  : A2;
    const __nv_bfloat16* Bw = (z == 0) ? Bw0 : (z == 1) ? Bw1 : Bw2;
    void* Cv                = (z == 0) ? C0v : (z == 1) ? C1v : C2v;

    const int t   = threadIdx.x;
    const int wid = t >> 5;
    const int wm  = wid & 1;
    const int wn  = wid >> 1;
    const int m0  = blockIdx.y * 128, n0 = blockIdx.x * 128;

    const __nv_bfloat16* Abase = A  + (size_t)m0 * KSTORE;
    const __nv_bfloat16* Bbase = Bw + (size_t)n0 * KSTORE;
    const uint32_t sAb = smem_u32(sA), sBb = smem_u32(sB);

    wmma::fragment<wmma::accumulator, 16, 16, 16, float> cf[4][2];
    #pragma unroll
    for (int i = 0; i < 4; i++)
        #pragma unroll
        for (int j = 0; j < 2; j++) wmma::fill_fragment(cf[i][j], 0.f);

    // prologue: kt=0 (A slot 0 + B slot 0), kt=1 (B slot 1 only)
    tile_loads(Abase + kt_aoff(0), sAb, t);
    tile_loads(Bbase + kt_boff(0), sBb, t);
    asm volatile("cp.async.commit_group;");
    tile_loads(Bbase + kt_boff(1), sBb + 1 * (B_ELEMS * 2), t);
    asm volatile("cp.async.commit_group;");

    #pragma unroll 1
    for (int kt = 0; kt < NKT; kt++) {
        asm volatile("cp.async.wait_group 1;");
        __syncthreads();
        if (kt + 2 < NKT) {
            if (kt_aload(kt + 2))
                tile_loads(Abase + kt_aoff(kt + 2),
                           sAb + (kt_aidx(kt + 2) % 3) * (A_ELEMS * 2), t);
            tile_loads(Bbase + kt_boff(kt + 2),
                       sBb + ((kt + 2) % 3) * (B_ELEMS * 2), t);
        }
        asm volatile("cp.async.commit_group;");

        const __nv_bfloat16* sa = sA + (kt_aidx(kt) % 3) * A_ELEMS;
        const __nv_bfloat16* sb = sB + (kt % 3) * B_ELEMS;
        #pragma unroll
        for (int kk = 0; kk < BK; kk += 16) {
            wmma::fragment<wmma::matrix_a, 16, 16, 16, __nv_bfloat16,
                           wmma::row_major> af[4];
            wmma::fragment<wmma::matrix_b, 16, 16, 16, __nv_bfloat16,
                           wmma::col_major> bf[2];
            #pragma unroll
            for (int i = 0; i < 4; i++)
                wmma::load_matrix_sync(af[i],
                    sa + (wm * 64 + i * 16) * STR + kk, STR);
            #pragma unroll
            for (int j = 0; j < 2; j++)
                wmma::load_matrix_sync(bf[j],
                    sb + (wn * 32 + j * 16) * STR + kk, STR);
            #pragma unroll
            for (int i = 0; i < 4; i++)
                #pragma unroll
                for (int j = 0; j < 2; j++)
                    wmma::mma_sync(cf[i][j], af[i], bf[j], cf[i][j]);
        }
    }

    if (!SPLITOUT) {
        float* C = (float*)Cv;
        #pragma unroll
        for (int i = 0; i < 4; i++)
            #pragma unroll
            for (int j = 0; j < 2; j++)
                wmma::store_matrix_sync(
                    C + (size_t)(m0 + wm * 64 + i * 16) * D_
                      + n0 + wn * 32 + j * 16,
                    cf[i][j], D_, wmma::mem_row_major);
    } else {
        // stage fp32 tile in smem, then split-write bf16 [hi|lo] per head
        float* stage = (float*)gsm;            // 128 x 132 fp32 = 67584 B
        __syncthreads();                        // mainloop smem reads done
        #pragma unroll
        for (int i = 0; i < 4; i++)
            #pragma unroll
            for (int j = 0; j < 2; j++)
                wmma::store_matrix_sync(
                    stage + (wm * 64 + i * 16) * 132 + wn * 32 + j * 16,
                    cf[i][j], 132, wmma::mem_row_major);
        __syncthreads();
        __nv_bfloat16* Cb = (__nv_bfloat16*)Cv;
        for (int i = t; i < 128 * 32; i += 256) {
            int row = i >> 5, c4 = (i & 31) << 2;      // tile col 0..124
            float4 x = *(float4*)&stage[row * 132 + c4];
            uint2 hi2, lo2;
            split4(x, hi2, lo2);
            int gcol = n0 + c4;
            int h = gcol >> 6, c6 = gcol & 63;
            __nv_bfloat16* dp = Cb + ((size_t)(m0 + row) * H_ + h) * 128 + c6;
            *(uint2*)(dp)      = hi2;
            *(uint2*)(dp + 64) = lo2;
        }
    }
}

// ---------------------------------------------------------------------------
// wmma banded local attention. Load phase is now pure cp.async from the
// pre-split g_qkv2 layout (hi/lo 128B chunks per row per head); OOB K/V rows
// zero-filled via cp.async src-size 0. MMA/softmax/epilogue unchanged.
// ---------------------------------------------------------------------------
#define AQLD 72
#define ASLD 84
#define APLD 88
#define AOLD 68

#define AOFF_Q 0
#define AOFF_K (AOFF_Q + 2 * 64 * AQLD * 2)
#define AOFF_V (AOFF_K + 2 * 128 * AQLD * 2)
#define AOFF_S (AOFF_V + 2 * 128 * AQLD * 2)
#define SMEM_ATTN (AOFF_S + 64 * ASLD * 4)         // 113664

__global__ __launch_bounds__(256, 2) void attn_wmma_kernel(
    const __nv_bfloat16* __restrict__ Qkv2, const unsigned char* __restrict__ mask,
    __nv_bfloat16* __restrict__ Out2)
{
    extern __shared__ __align__(256) char sm[];
    __nv_bfloat16* sQhi = (__nv_bfloat16*)(sm + AOFF_Q);
    __nv_bfloat16* sQlo = sQhi + 64 * AQLD;
    __nv_bfloat16* sKhi = (__nv_bfloat16*)(sm + AOFF_K);
    __nv_bfloat16* sKlo = sKhi + 128 * AQLD;
    __nv_bfloat16* sVhi = (__nv_bfloat16*)(sm + AOFF_V);
    __nv_bfloat16* sVlo = sVhi + 128 * AQLD;
    float*         sS   = (float*)(sm + AOFF_S);
    __nv_bfloat16* sPhi = (__nv_bfloat16*)(sm + AOFF_Q);   // aliases dead Q+K
    __nv_bfloat16* sPlo = sPhi + 64 * APLD;
    float*         sO   = sS;                               // aliases dead S

    const int l0 = blockIdx.x * 64;
    const int h  = blockIdx.y;
    const int b  = blockIdx.z;
    const int t  = threadIdx.x;
    const int w  = t >> 5;

    const uint32_t uQhi = smem_u32(sQhi), uQlo = smem_u32(sQlo);
    const uint32_t uKhi = smem_u32(sKhi), uKlo = smem_u32(sKlo);
    const uint32_t uVhi = smem_u32(sVhi), uVlo = smem_u32(sVlo);

    // per-(tensor,row,head) base: ((s*M + b*L + l)*H + h)*128
    const __nv_bfloat16* Qb = Qkv2 + ((size_t)(b * L_) * H_ + h) * 128;
    const __nv_bfloat16* Kb = Qkv2 + ((size_t)(M_ + b * L_) * H_ + h) * 128;
    const __nv_bfloat16* Vb = Qkv2 + ((size_t)(2 * M_ + b * L_) * H_ + h) * 128;

    // ---- Q: 64 rows x (8 hi + 8 lo) 16B chunks ----
    for (int i = t; i < 64 * 16; i += 256) {
        int row = i >> 4, ch = i & 15;
        int p = ch >> 3, cc = ch & 7;
        const __nv_bfloat16* src = Qb + (size_t)(l0 + row) * (H_ * 128)
                                      + p * 64 + cc * 8;
        uint32_t dst = (p ? uQlo : uQhi) + (uint32_t)(row * (AQLD * 2) + cc * 16);
        cp16(dst, src);
    }
    // ---- K & V windows: 128 rows each, OOB rows zero-filled ----
    for (int i = t; i < 128 * 16; i += 256) {
        int row = i >> 4, ch = i & 15;
        int p = ch >> 3, cc = ch & 7;
        int gl = l0 - PADF + row;
        bool in = (gl >= 0) && (gl < L_);
        int gls = in ? gl : 0;
        uint32_t sz = in ? 16u : 0u;
        size_t off = (size_t)gls * (H_ * 128) + p * 64 + cc * 8;
        uint32_t doff = (uint32_t)(row * (AQLD * 2) + cc * 16);
        cp16z((p ? uKlo : uKhi) + doff, Kb + off, sz);
        cp16z((p ? uVlo : uVhi) + doff, Vb + off, sz);
    }
    asm volatile("cp.async.commit_group;");
    asm volatile("cp.async.wait_group 0;");
    __syncthreads();

    // ---- S (banded): row group rg = w>>1, col tiles split 3/2 across halves.
    {
        const int rg   = w >> 1;
        const int half = w & 1;
        const int j0   = half ? 3 : 0;
        const int nj   = half ? 2 : 3;

        wmma::fragment<wmma::accumulator, 16, 16, 16, float> sf[3];
        #pragma unroll
        for (int j = 0; j < 3; j++) wmma::fill_fragment(sf[j], 0.f);

        #pragma unroll
        for (int tm = 0; tm < 3; tm++) {
            const __nv_bfloat16* Qsrc = (tm == 2) ? sQlo : sQhi;
            const __nv_bfloat16* Ksrc = (tm == 1) ? sKlo : sKhi;
            #pragma unroll
            for (int kk = 0; kk < 64; kk += 16) {
                wmma::fragment<wmma::matrix_a, 16, 16, 16, __nv_bfloat16,
                               wmma::row_major> qa;
                wmma::load_matrix_sync(qa, Qsrc + rg * 16 * AQLD + kk, AQLD);
                #pragma unroll
                for (int j = 0; j < 3; j++) {
                    if (j < nj) {
                        wmma::fragment<wmma::matrix_b, 16, 16, 16, __nv_bfloat16,
                                       wmma::col_major> kb;
                        wmma::load_matrix_sync(kb,
                            Ksrc + (rg * 16 + (j0 + j) * 16) * AQLD + kk, AQLD);
                        wmma::mma_sync(sf[j], qa, kb, sf[j]);
                    }
                }
            }
        }
        #pragma unroll
        for (int j = 0; j < 3; j++)
            if (j < nj)
                wmma::store_matrix_sync(sS + rg * 16 * ASLD + (j0 + j) * 16,
                                        sf[j], ASLD, wmma::mem_row_major);
    }
    __syncthreads();

    // ---- softmax per query row; write banded split P ----
    {
        const int g     = t >> 2;
        const int lane4 = t & 3;
        const int G     = g >> 4;
        const int off   = g & 15;
        const int gl0   = l0 - PADF + 16 * G;
        const unsigned char* mrow = mask + (size_t)b * L_;

        float sv[16];
        #pragma unroll
        for (int i = 0; i < 16; i++) {
            int r  = off + lane4 * 16 + i;
            int gl = gl0 + r;
            bool valid = (gl >= 0) && (gl < L_) && (mrow[gl] == 0);
            sv[i] = valid ? sS[g * ASLD + r] : -1e30f;
        }
        float m = sv[0];
        #pragma unroll
        for (int i = 1; i < 16; i++) m = fmaxf(m, sv[i]);
        m = fmaxf(m, __shfl_xor_sync(0xffffffffu, m, 1));
        m = fmaxf(m, __shfl_xor_sync(0xffffffffu, m, 2));
        float sum = 0.f;
        #pragma unroll
        for (int i = 0; i < 16; i++) { sv[i] = __expf(sv[i] - m); sum += sv[i]; }
        sum += __shfl_xor_sync(0xffffffffu, sum, 1);
        sum += __shfl_xor_sync(0xffffffffu, sum, 2);
        float inv = 1.f / sum;

        __nv_bfloat16 z0 = __float2bfloat16(0.f);
        #pragma unroll
        for (int i = 0; i < 20; i++) {
            int r = lane4 * 20 + i;
            sPhi[g * APLD + r] = z0;
            sPlo[g * APLD + r] = z0;
        }
        #pragma unroll
        for (int i = 0; i < 16; i++) {
            int r = off + lane4 * 16 + i;
            __nv_bfloat16 hi, lo;
            split2(sv[i] * inv, hi, lo);
            sPhi[g * APLD + r] = hi;
            sPlo[g * APLD + r] = lo;
        }
    }
    __syncthreads();

    // ---- O = P @ V (banded, compensated) ----
    {
        const int rg   = w >> 1;
        const int half = w & 1;

        wmma::fragment<wmma::accumulator, 16, 16, 16, float> of[2];
        #pragma unroll
        for (int j = 0; j < 2; j++) wmma::fill_fragment(of[j], 0.f);

        #pragma unroll
        for (int tm = 0; tm < 3; tm++) {
            const __nv_bfloat16* Psrc = (tm == 2) ? sPlo : sPhi;
            const __nv_bfloat16* Vsrc = (tm == 1) ? sVlo : sVhi;
            #pragma unroll
            for (int kk = 0; kk < 80; kk += 16) {
                wmma::fragment<wmma::matrix_a, 16, 16, 16, __nv_bfloat16,
                               wmma::row_major> pa;
                wmma::load_matrix_sync(pa, Psrc + rg * 16 * APLD + kk, APLD);
                #pragma unroll
                for (int j = 0; j < 2; j++) {
                    wmma::fragment<wmma::matrix_b, 16, 16, 16, __nv_bfloat16,
                                   wmma::row_major> vb;
                    wmma::load_matrix_sync(vb,
                        Vsrc + (rg * 16 + kk) * AQLD + (half * 2 + j) * 16, AQLD);
                    wmma::mma_sync(of[j], pa, vb, of[j]);
                }
            }
        }
        #pragma unroll
        for (int j = 0; j < 2; j++)
            wmma::store_matrix_sync(sO + rg * 16 * AOLD + (half * 2 + j) * 16,
                                    of[j], AOLD, wmma::mem_row_major);
    }
    __syncthreads();

    // ---- epilogue: split O straight into g_attn2 [hi|lo] (vectorized) ----
    for (int i = t; i < 64 * 16; i += 256) {
        int row = i >> 4, c = (i & 15) << 2;
        float4 x = *(const float4*)(sO + row * AOLD + c);
        uint2 hi2, lo2;
        split4(x, hi2, lo2);
        __nv_bfloat16* dst = Out2 + (size_t)(b * L_ + l0 + row) * KSTORE
                                  + h * EK_ + c;
        *(uint2*)(dst)       = hi2;
        *(uint2*)(dst + 512) = lo2;
    }
}

// ---------------------------------------------------------------------------
// Launch
// ---------------------------------------------------------------------------
extern "C" void kernel_launch(void* const* d_in, const int* in_sizes, int n_in,
                              void* d_out, int out_size)
{
    const float* query = (const float*)d_in[0];
    const float* key   = (const float*)d_in[1];
    const float* value = (const float*)d_in[2];
    const unsigned char* mask = (const unsigned char*)d_in[3];
    const float* Wq = (const float*)d_in[5];
    const float* Wk = (const float*)d_in[6];
    const float* Wv = (const float*)d_in[7];
    const float* Wo = (const float*)d_in[8];
    float* out = (float*)d_out;

    __nv_bfloat16 *dqkv2, *din2, *dat2, *dw2;
    cudaGetSymbolAddress((void**)&dqkv2, g_qkv2);
    cudaGetSymbolAddress((void**)&din2, g_in2);
    cudaGetSymbolAddress((void**)&dat2, g_attn2);
    cudaGetSymbolAddress((void**)&dw2, g_w2);

    cudaFuncSetAttribute(attn_wmma_kernel,
                         cudaFuncAttributeMaxDynamicSharedMemorySize, SMEM_ATTN);
    cudaFuncSetAttribute(gemm3_kernel<true>,
                         cudaFuncAttributeMaxDynamicSharedMemorySize, GEMM_SMEM);
    cudaFuncSetAttribute(gemm3_kernel<false>,
                         cudaFuncAttributeMaxDynamicSharedMemorySize, GEMM_SMEM);

    // 1) split inputs + weights into [hi|lo] bf16
    split_in_kernel<<<dim3(M_ * D_ / 1024, 3), 256>>>(query, key, value);
    split_w_kernel<<<dim3(8, 8, 4), 256>>>(Wq, Wk, Wv, Wo);

    // 2) QKV projections: 3 GEMMs, split-bf16 epilogue into g_qkv2
    const __nv_bfloat16* Aq = din2;
    const __nv_bfloat16* Ak = din2 + (size_t)1 * M_ * KSTORE;
    const __nv_bfloat16* Av = din2 + (size_t)2 * M_ * KSTORE;
    const __nv_bfloat16* Bq = dw2;
    const __nv_bfloat16* Bk = dw2 + (size_t)1 * D_ * KSTORE;
    const __nv_bfloat16* Bv = dw2 + (size_t)2 * D_ * KSTORE;
    const __nv_bfloat16* Bo = dw2 + (size_t)3 * D_ * KSTORE;
    __nv_bfloat16* Q2 = dqkv2;
    __nv_bfloat16* K2 = dqkv2 + (size_t)1 * M_ * QROW;
    __nv_bfloat16* V2 = dqkv2 + (size_t)2 * M_ * QROW;
    gemm3_kernel<true><<<dim3(D_ / 128, M_ / 128, 3), 256, GEMM_SMEM>>>(
        Aq, Ak, Av, Bq, Bk, Bv, Q2, K2, V2);

    // 3) banded local attention: cp.async loads from pre-split g_qkv2
    attn_wmma_kernel<<<dim3(16, 8, 4), 256, SMEM_ATTN>>>(dqkv2, mask, dat2);

    // 4) output projection (fp32 epilogue to d_out)
    gemm3_kernel<false><<<dim3(D_ / 128, M_ / 128, 1), 256, GEMM_SMEM>>>(
        dat2, dat2, dat2, Bo, Bo, Bo, out, out, out);
}